// round 1
// baseline (speedup 1.0000x reference)
#include <cuda_runtime.h>

// ---------------------------------------------------------------------------
// RiemannianGraph_HRSNN — spiking GCN over T=15 steps, B=2048, N=64 nodes.
//
// Key algebraic reductions (see analysis):
//   x = X*Wproj + bproj is rank-1 in features  ->  layer-1 conv is analytic:
//       cur1[n,f] = S[n,t]*p1[f] + rowL[n]*q1[f] + bg1[f],  S = L @ X_t
//   spk1 = s_int + rank-1 terms  ->  layer-2 conv:
//       cur2 = (L @ s_int) @ Wg2 + S_t (x) p2 + rowL (x) q2 + bg2
//   mem_li + DP window  ->  fixed coeff[t] weighting of spikes; the skip GEMM
//       (acc1 @ Ws2) runs once per batch.
// ---------------------------------------------------------------------------

#define TSTEPS 15

// scratch: dp features [B=2048, 4096] fp32
__device__ float g_dp[2048 * 4096];
// derived constants:
// [0:32) p1 [32:64) q1 [64:96) ps1 [96:128) cs1
// [128:192) p2 [192:256) q2 [256:320) ps2 [320:384) qs2
// [384:399) coeff[15], [399] csum
__device__ float g_const[512];

// ---------------------------------------------------------------------------
__global__ void prep_kernel(const float* __restrict__ Wproj,
                            const float* __restrict__ bproj,
                            const float* __restrict__ Wg1,
                            const float* __restrict__ Ws1,
                            const float* __restrict__ bs1,
                            const float* __restrict__ Wg2,
                            const float* __restrict__ Ws2,
                            const float* __restrict__ bs2) {
    int t = threadIdx.x;
    if (t < 32) {
        float p1 = 0.f, q1 = 0.f, ps1 = 0.f, cs1 = 0.f;
        #pragma unroll
        for (int k = 0; k < 16; k++) {
            p1  += Wproj[k] * Wg1[k * 32 + t];
            q1  += bproj[k] * Wg1[k * 32 + t];
            ps1 += Wproj[k] * Ws1[k * 32 + t];
            cs1 += bproj[k] * Ws1[k * 32 + t];
        }
        cs1 += bs1[t];
        g_const[t]       = p1;
        g_const[32 + t]  = q1;
        g_const[64 + t]  = ps1;
        g_const[96 + t]  = cs1;
    }
    __syncthreads();
    if (t < 64) {
        float p2 = 0.f, q2 = 0.f, ps2 = 0.f, qs2 = 0.f;
        #pragma unroll
        for (int f = 0; f < 32; f++) {
            float a = g_const[64 + f];
            float c = g_const[96 + f];
            p2  += a * Wg2[f * 64 + t];
            q2  += c * Wg2[f * 64 + t];
            ps2 += a * Ws2[f * 64 + t];
            qs2 += c * Ws2[f * 64 + t];
        }
        qs2 += bs2[t];
        g_const[128 + t] = p2;
        g_const[192 + t] = q2;
        g_const[256 + t] = ps2;
        g_const[320 + t] = qs2;
    }
    if (t == 0) {
        float pw[TSTEPS];
        pw[0] = 1.f;
        for (int k = 1; k < TSTEPS; k++) pw[k] = pw[k - 1] * 0.9f;
        float cs = 0.f;
        for (int tau = 0; tau < TSTEPS; tau++) {
            float late = 0.f, early = 0.f;
            for (int s = 10; s < 15; s++) if (s >= tau) late  += pw[s - tau];
            for (int s = 0;  s < 5;  s++) if (s >= tau) early += pw[s - tau];
            float c = 0.2f * (late - early);
            g_const[384 + tau] = c;
            cs += c;
        }
        g_const[399] = cs;   // contiguous with coeff: coef[15] = csum
    }
}

// ---------------------------------------------------------------------------
__device__ __forceinline__ float lif_step(float& m, float cur, float beta, float thr) {
    float r = (m > thr) ? thr : 0.f;      // reset from previous mem (subtract)
    m = beta * m + cur - r;
    return (m > thr) ? 1.f : 0.f;
}

// smem layout (floats)
#define SM_LT    0        // 64x64 L transposed: Lt[m][n]
#define SM_S1S   4096     // 64x32 spike sums layer1 (s_int)
#define SM_PT    6144     // 32x64 P transposed: Pt[f][n]
#define SM_WG2   8192     // 32x64
#define SM_WS2   10240    // 32x64
#define SM_SS    12288    // 64x16  S[n][t]
#define SM_XS    13312    // 15x64
#define SM_ROWL  14272    // 64
#define SM_AX    14336    // 64
#define SM_P1    14400
#define SM_Q1    14432
#define SM_BG1   14464
#define SM_P2    14496
#define SM_Q2    14560
#define SM_BG2   14624
#define SM_PS2   14688
#define SM_QS2   14752
#define SM_COEF  14816    // 16 (coeff[0..14], csum)
#define SM_TOTAL 14832

__global__ void __launch_bounds__(256, 1)
main_kernel(const float* __restrict__ L, const float* __restrict__ X,
            const float* __restrict__ bg1, const float* __restrict__ Wg2,
            const float* __restrict__ bg2, const float* __restrict__ Ws2) {
    extern __shared__ float sm[];
    float* Lt   = sm + SM_LT;
    float* s1s  = sm + SM_S1S;
    float* Pt   = sm + SM_PT;
    float* Wg2s = sm + SM_WG2;
    float* Ws2s = sm + SM_WS2;
    float* Ssm  = sm + SM_SS;
    float* Xs   = sm + SM_XS;
    float* rowL = sm + SM_ROWL;
    float* axs  = sm + SM_AX;
    float* coef = sm + SM_COEF;

    const int tid = threadIdx.x;
    const int b = blockIdx.x;
    const float* Lb = L + (size_t)b * 4096;
    const float* Xb = X + (size_t)b * (TSTEPS * 64);

    // ---- load L transposed ----
    {
        int n  = tid >> 2;
        int m0 = (tid & 3) * 16;
        #pragma unroll
        for (int q = 0; q < 4; q++) {
            float4 v = *(const float4*)(Lb + n * 64 + m0 + q * 4);
            Lt[(m0 + q * 4 + 0) * 64 + n] = v.x;
            Lt[(m0 + q * 4 + 1) * 64 + n] = v.y;
            Lt[(m0 + q * 4 + 2) * 64 + n] = v.z;
            Lt[(m0 + q * 4 + 3) * 64 + n] = v.w;
        }
    }
    for (int i = tid; i < TSTEPS * 64; i += 256) Xs[i] = Xb[i];
    for (int i = tid; i < 2048; i += 256) { Wg2s[i] = Wg2[i]; Ws2s[i] = Ws2[i]; }
    if (tid < 32) {
        sm[SM_P1 + tid]  = g_const[tid];
        sm[SM_Q1 + tid]  = g_const[32 + tid];
        sm[SM_BG1 + tid] = bg1[tid];
    } else if (tid < 96) {
        int g = tid - 32;
        sm[SM_P2 + g]  = g_const[128 + g];
        sm[SM_Q2 + g]  = g_const[192 + g];
        sm[SM_PS2 + g] = g_const[256 + g];
        sm[SM_QS2 + g] = g_const[320 + g];
        sm[SM_BG2 + g] = bg2[g];
    } else if (tid < 112) {
        coef[tid - 96] = g_const[384 + (tid - 96)];
    }
    __syncthreads();

    // ---- S[n][t] = sum_m L[n,m] X[t,m]; rowL[n] = sum_m L[n,m] ----
    for (int idx = tid; idx < 1024; idx += 256) {
        int n = idx >> 4, tt = idx & 15;
        float acc = 0.f;
        if (tt < TSTEPS) {
            const float* xr = Xs + tt * 64;
            #pragma unroll 8
            for (int m = 0; m < 64; m++) acc += Lt[m * 64 + n] * xr[m];
            Ssm[n * 16 + tt] = acc;
        } else {
            #pragma unroll 8
            for (int m = 0; m < 64; m++) acc += Lt[m * 64 + n];
            rowL[n] = acc;
        }
    }
    __syncthreads();

    // ---- per-thread hoisted constants / register state ----
    const int lane = tid & 31, wA = tid >> 5;     // layout A: f=lane, n=8*wA+i
    const float p1f  = sm[SM_P1 + lane];
    const float q1f  = sm[SM_Q1 + lane];
    const float bg1f = sm[SM_BG1 + lane];
    float rowLa[8];
    #pragma unroll
    for (int i = 0; i < 8; i++) rowLa[i] = rowL[wA * 8 + i];
    float m1a[8], m1b[8], m1c[8], a1[8];
    #pragma unroll
    for (int i = 0; i < 8; i++) { m1a[i] = m1b[i] = m1c[i] = a1[i] = 0.f; }

    const int iB = tid & 15, jB = tid >> 4;       // layout B (GEMM1) & C (GEMM2)
    float rowLc[4], p2c[4], q2c[4], bg2c[4], ps2c[4], qs2c[4];
    #pragma unroll
    for (int c = 0; c < 4; c++) {
        rowLc[c] = rowL[iB * 4 + c];
        p2c[c]  = sm[SM_P2 + jB * 4 + c];
        q2c[c]  = sm[SM_Q2 + jB * 4 + c];
        bg2c[c] = sm[SM_BG2 + jB * 4 + c];
        ps2c[c] = sm[SM_PS2 + jB * 4 + c];
        qs2c[c] = sm[SM_QS2 + jB * 4 + c];
    }
    float m2a[16], m2b[16], m2c_[16], a2[16];
    #pragma unroll
    for (int e = 0; e < 16; e++) { m2a[e] = m2b[e] = m2c_[e] = a2[e] = 0.f; }

    // ======================= time loop =======================
    for (int t = 0; t < TSTEPS; t++) {
        const float ct = coef[t];

        // ---- phase 1: analytic cur1 + triple LIF -> s_int (layout A) ----
        #pragma unroll
        for (int i = 0; i < 8; i++) {
            int n = wA * 8 + i;
            float cur = Ssm[n * 16 + t] * p1f + rowLa[i] * q1f + bg1f;
            float s = 0.f;
            s += lif_step(m1a[i], cur, 0.80f, 0.8f);
            s += lif_step(m1b[i], cur, 0.90f, 1.0f);
            s += lif_step(m1c[i], cur, 0.95f, 1.5f);
            a1[i] += ct * s;
            s1s[n * 32 + lane] = s;
        }
        __syncthreads();

        // ---- phase 2: P = L @ s_int (64x64 @ 64x32), 4x2 register tile ----
        float p00 = 0.f, p10 = 0.f, p20 = 0.f, p30 = 0.f;
        float p01 = 0.f, p11 = 0.f, p21 = 0.f, p31 = 0.f;
        #pragma unroll 8
        for (int m = 0; m < 64; m++) {
            float4 lv = *(const float4*)(Lt + m * 64 + iB * 4);
            float2 sv = *(const float2*)(s1s + m * 32 + jB * 2);
            p00 += lv.x * sv.x; p10 += lv.y * sv.x; p20 += lv.z * sv.x; p30 += lv.w * sv.x;
            p01 += lv.x * sv.y; p11 += lv.y * sv.y; p21 += lv.z * sv.y; p31 += lv.w * sv.y;
        }
        *(float4*)(Pt + (jB * 2 + 0) * 64 + iB * 4) = make_float4(p00, p10, p20, p30);
        *(float4*)(Pt + (jB * 2 + 1) * 64 + iB * 4) = make_float4(p01, p11, p21, p31);
        __syncthreads();

        // ---- phase 3: cur2 = P @ Wg2 + rank-1 terms; triple LIF2 ----
        float c2[4][4];
        #pragma unroll
        for (int r = 0; r < 4; r++)
            #pragma unroll
            for (int c = 0; c < 4; c++) c2[r][c] = 0.f;

        #pragma unroll 8
        for (int f = 0; f < 32; f++) {
            float4 pv = *(const float4*)(Pt + f * 64 + iB * 4);
            float4 wv = *(const float4*)(Wg2s + f * 64 + jB * 4);
            c2[0][0] += pv.x * wv.x; c2[0][1] += pv.x * wv.y; c2[0][2] += pv.x * wv.z; c2[0][3] += pv.x * wv.w;
            c2[1][0] += pv.y * wv.x; c2[1][1] += pv.y * wv.y; c2[1][2] += pv.y * wv.z; c2[1][3] += pv.y * wv.w;
            c2[2][0] += pv.z * wv.x; c2[2][1] += pv.z * wv.y; c2[2][2] += pv.z * wv.z; c2[2][3] += pv.z * wv.w;
            c2[3][0] += pv.w * wv.x; c2[3][1] += pv.w * wv.y; c2[3][2] += pv.w * wv.z; c2[3][3] += pv.w * wv.w;
        }
        #pragma unroll
        for (int r = 0; r < 4; r++) {
            int n = iB * 4 + r;
            float sc = Ssm[n * 16 + t];
            #pragma unroll
            for (int c = 0; c < 4; c++) {
                float cur = c2[r][c] + sc * p2c[c] + rowLc[r] * q2c[c] + bg2c[c];
                int e = r * 4 + c;
                float s = 0.f;
                s += lif_step(m2a[e],  cur, 0.80f, 0.8f);
                s += lif_step(m2b[e],  cur, 0.90f, 1.0f);
                s += lif_step(m2c_[e], cur, 0.95f, 1.5f);
                a2[e] += ct * s;
            }
        }
    }

    // ======================= batch epilogue =======================
    __syncthreads();                       // Pt free (last GEMM2 done)
    #pragma unroll
    for (int i = 0; i < 8; i++)            // A1t[f][n] = acc1 (layout A)
        Pt[lane * 64 + wA * 8 + i] = a1[i];
    if (tid < 64) {                        // ax[n] = sum_t coeff[t] X[t,n]
        float acc = 0.f;
        #pragma unroll
        for (int t = 0; t < TSTEPS; t++) acc += coef[t] * Xs[t * 64 + tid];
        axs[tid] = acc;
    }
    __syncthreads();

    float dpv[4][4];
    #pragma unroll
    for (int r = 0; r < 4; r++)
        #pragma unroll
        for (int c = 0; c < 4; c++) dpv[r][c] = a2[r * 4 + c];

    #pragma unroll 8
    for (int f = 0; f < 32; f++) {         // + acc1 @ Ws2
        float4 pv = *(const float4*)(Pt + f * 64 + iB * 4);
        float4 wv = *(const float4*)(Ws2s + f * 64 + jB * 4);
        dpv[0][0] += pv.x * wv.x; dpv[0][1] += pv.x * wv.y; dpv[0][2] += pv.x * wv.z; dpv[0][3] += pv.x * wv.w;
        dpv[1][0] += pv.y * wv.x; dpv[1][1] += pv.y * wv.y; dpv[1][2] += pv.y * wv.z; dpv[1][3] += pv.y * wv.w;
        dpv[2][0] += pv.z * wv.x; dpv[2][1] += pv.z * wv.y; dpv[2][2] += pv.z * wv.z; dpv[2][3] += pv.z * wv.w;
        dpv[3][0] += pv.w * wv.x; dpv[3][1] += pv.w * wv.y; dpv[3][2] += pv.w * wv.z; dpv[3][3] += pv.w * wv.w;
    }
    const float csum = coef[15];
    #pragma unroll
    for (int r = 0; r < 4; r++) {
        int n = iB * 4 + r;
        float axv = axs[n];
        float4 o;
        o.x = dpv[r][0] + axv * ps2c[0] + csum * qs2c[0];
        o.y = dpv[r][1] + axv * ps2c[1] + csum * qs2c[1];
        o.z = dpv[r][2] + axv * ps2c[2] + csum * qs2c[2];
        o.w = dpv[r][3] + axv * ps2c[3] + csum * qs2c[3];
        *(float4*)(g_dp + (size_t)b * 4096 + n * 64 + jB * 4) = o;
    }
}

// ---------------------------------------------------------------------------
// decoder: out = relu(dp @ Wc1 + bc1) @ Wc2 + bc2   [2048,4096]->[2048,4]
// CTA = 16 batch rows, 256 threads.
__global__ void __launch_bounds__(256)
decoder_kernel(const float* __restrict__ Wc1, const float* __restrict__ bc1,
               const float* __restrict__ Wc2, const float* __restrict__ bc2,
               float* __restrict__ out) {
    __shared__ float Wc1s[64 * 128];
    __shared__ float dpT[64 * 16];
    __shared__ float hs[16 * 128];
    __shared__ float Wc2s[128 * 4];
    __shared__ float bc1s[128];

    const int tid = threadIdx.x;
    const int b0 = blockIdx.x * 16;
    if (tid < 128) bc1s[tid] = bc1[tid];
    for (int i = tid; i < 512; i += 256) Wc2s[i] = Wc2[i];

    const int j = tid & 127, rh = tid >> 7;
    float h[8];
    #pragma unroll
    for (int r = 0; r < 8; r++) h[r] = 0.f;

    for (int k0 = 0; k0 < 4096; k0 += 64) {
        __syncthreads();
        #pragma unroll
        for (int p = 0; p < 8; p++) {       // Wc1 chunk [64][128]
            int f4 = tid + p * 256;
            int kk = f4 >> 5, jq = f4 & 31;
            *(float4*)(Wc1s + kk * 128 + jq * 4) =
                *(const float4*)(Wc1 + (size_t)(k0 + kk) * 128 + jq * 4);
        }
        {                                    // dp chunk transposed [64][16]
            int r = tid >> 4, kq = tid & 15;
            float4 v = *(const float4*)(g_dp + (size_t)(b0 + r) * 4096 + k0 + kq * 4);
            dpT[(kq * 4 + 0) * 16 + r] = v.x;
            dpT[(kq * 4 + 1) * 16 + r] = v.y;
            dpT[(kq * 4 + 2) * 16 + r] = v.z;
            dpT[(kq * 4 + 3) * 16 + r] = v.w;
        }
        __syncthreads();
        #pragma unroll 4
        for (int kk = 0; kk < 64; kk++) {
            float w = Wc1s[kk * 128 + j];
            float4 d0 = *(const float4*)(dpT + kk * 16 + rh * 8);
            float4 d1 = *(const float4*)(dpT + kk * 16 + rh * 8 + 4);
            h[0] += d0.x * w; h[1] += d0.y * w; h[2] += d0.z * w; h[3] += d0.w * w;
            h[4] += d1.x * w; h[5] += d1.y * w; h[6] += d1.z * w; h[7] += d1.w * w;
        }
    }
    __syncthreads();
    #pragma unroll
    for (int r = 0; r < 8; r++) {
        float v = h[r] + bc1s[j];
        hs[(rh * 8 + r) * 128 + j] = v > 0.f ? v : 0.f;
    }
    __syncthreads();
    if (tid < 64) {
        int r = tid >> 2, c = tid & 3;
        float acc = bc2[c];
        #pragma unroll 8
        for (int jj = 0; jj < 128; jj++) acc += hs[r * 128 + jj] * Wc2s[jj * 4 + c];
        out[(b0 + r) * 4 + c] = acc;
    }
}

// ---------------------------------------------------------------------------
extern "C" void kernel_launch(void* const* d_in, const int* in_sizes, int n_in,
                              void* d_out, int out_size) {
    const float* L     = (const float*)d_in[0];
    const float* X     = (const float*)d_in[1];
    const float* Wproj = (const float*)d_in[2];
    const float* bproj = (const float*)d_in[3];
    const float* Wg1   = (const float*)d_in[4];
    const float* bg1   = (const float*)d_in[5];
    const float* Ws1   = (const float*)d_in[6];
    const float* bs1   = (const float*)d_in[7];
    const float* Wg2   = (const float*)d_in[8];
    const float* bg2   = (const float*)d_in[9];
    const float* Ws2   = (const float*)d_in[10];
    const float* bs2   = (const float*)d_in[11];
    const float* Wc1   = (const float*)d_in[12];
    const float* bc1   = (const float*)d_in[13];
    const float* Wc2   = (const float*)d_in[14];
    const float* bc2   = (const float*)d_in[15];
    float* out = (float*)d_out;

    int B = in_sizes[0] / 4096;   // 2048
    if (B > 2048) B = 2048;

    static const size_t smem_bytes = SM_TOTAL * sizeof(float);
    cudaFuncSetAttribute(main_kernel, cudaFuncAttributeMaxDynamicSharedMemorySize,
                         (int)smem_bytes);

    prep_kernel<<<1, 64>>>(Wproj, bproj, Wg1, Ws1, bs1, Wg2, Ws2, bs2);
    main_kernel<<<B, 256, smem_bytes>>>(L, X, bg1, Wg2, bg2, Ws2);
    decoder_kernel<<<B / 16, 256>>>(Wc1, bc1, Wc2, bc2, out);
}

// round 3
// speedup vs baseline: 1.1083x; 1.1083x over previous
#include <cuda_runtime.h>
#include <cstdint>

// ---------------------------------------------------------------------------
// RiemannianGraph_HRSNN — spiking GCN, T=15, B=2048, N=64.
// Round 3: packed fp32 (fma.rn.f32x2 / FFMA2) GEMMs with duplicated-operand
// smem layouts; bitwise-identical math order vs R1. (R2 compile fix.)
// ---------------------------------------------------------------------------

#define TSTEPS 15

__device__ float g_dp[2048 * 4096];
__device__ float g_const[512];

typedef unsigned long long u64;

__device__ __forceinline__ u64 pk(float lo, float hi) {
    u64 d; asm("mov.b64 %0,{%1,%2};" : "=l"(d) : "f"(lo), "f"(hi)); return d;
}
__device__ __forceinline__ void upk(u64 v, float& lo, float& hi) {
    asm("mov.b64 {%0,%1},%2;" : "=f"(lo), "=f"(hi) : "l"(v));
}
__device__ __forceinline__ u64 f2(u64 a, u64 b, u64 c) {
    u64 d; asm("fma.rn.f32x2 %0,%1,%2,%3;" : "=l"(d) : "l"(a), "l"(b), "l"(c)); return d;
}
__device__ __forceinline__ u64 add2(u64 a, u64 b) {
    u64 d; asm("add.rn.f32x2 %0,%1,%2;" : "=l"(d) : "l"(a), "l"(b)); return d;
}
__device__ __forceinline__ void lds2(u64& a, u64& b, uint32_t addr) {
    asm volatile("ld.shared.v2.u64 {%0,%1},[%2];" : "=l"(a), "=l"(b) : "r"(addr));
}
__device__ __forceinline__ u64 lds1(uint32_t addr) {
    u64 a; asm volatile("ld.shared.b64 %0,[%1];" : "=l"(a) : "r"(addr)); return a;
}
__device__ __forceinline__ void sts2(uint32_t addr, u64 a, u64 b) {
    asm volatile("st.shared.v2.u64 [%0],{%1,%2};" :: "r"(addr), "l"(a), "l"(b));
}

// ---------------------------------------------------------------------------
__global__ void prep_kernel(const float* __restrict__ Wproj,
                            const float* __restrict__ bproj,
                            const float* __restrict__ Wg1,
                            const float* __restrict__ Ws1,
                            const float* __restrict__ bs1,
                            const float* __restrict__ Wg2,
                            const float* __restrict__ Ws2,
                            const float* __restrict__ bs2) {
    int t = threadIdx.x;
    if (t < 32) {
        float p1 = 0.f, q1 = 0.f, ps1 = 0.f, cs1 = 0.f;
        #pragma unroll
        for (int k = 0; k < 16; k++) {
            p1  += Wproj[k] * Wg1[k * 32 + t];
            q1  += bproj[k] * Wg1[k * 32 + t];
            ps1 += Wproj[k] * Ws1[k * 32 + t];
            cs1 += bproj[k] * Ws1[k * 32 + t];
        }
        cs1 += bs1[t];
        g_const[t]      = p1;
        g_const[32 + t] = q1;
        g_const[64 + t] = ps1;
        g_const[96 + t] = cs1;
    }
    __syncthreads();
    if (t < 64) {
        float p2 = 0.f, q2 = 0.f, ps2 = 0.f, qs2 = 0.f;
        #pragma unroll
        for (int f = 0; f < 32; f++) {
            float a = g_const[64 + f];
            float c = g_const[96 + f];
            p2  += a * Wg2[f * 64 + t];
            q2  += c * Wg2[f * 64 + t];
            ps2 += a * Ws2[f * 64 + t];
            qs2 += c * Ws2[f * 64 + t];
        }
        qs2 += bs2[t];
        g_const[128 + t] = p2;
        g_const[192 + t] = q2;
        g_const[256 + t] = ps2;
        g_const[320 + t] = qs2;
    }
    if (t == 0) {
        float pw[TSTEPS];
        pw[0] = 1.f;
        for (int k = 1; k < TSTEPS; k++) pw[k] = pw[k - 1] * 0.9f;
        float cs = 0.f;
        for (int tau = 0; tau < TSTEPS; tau++) {
            float late = 0.f, early = 0.f;
            for (int s = 10; s < 15; s++) if (s >= tau) late  += pw[s - tau];
            for (int s = 0;  s < 5;  s++) if (s >= tau) early += pw[s - tau];
            float c = 0.2f * (late - early);
            g_const[384 + tau] = c;
            cs += c;
        }
        g_const[399] = cs;
    }
}

// ---------------------------------------------------------------------------
__device__ __forceinline__ float lif_step(float& m, float cur, float beta, float thr) {
    float r = (m > thr) ? thr : 0.f;
    m = beta * m + (cur - r);
    return (m > thr) ? 1.f : 0.f;
}

// smem float offsets
#define SM_LT    0        // 64x64 Lt[m][n]
#define SM_S1D   4096     // 64x64 dup spikes s1d[m][2j](+1)  (reused: Ws2 dup in epilogue)
#define SM_PT    8192     // 32x64 Pt[f][n]
#define SM_WG2D  10240    // 32x128 dup Wg2
#define SM_ST    14336    // 16x64 St[t][n]
#define SM_XS    15360    // 15x64
#define SM_ROWL  16320
#define SM_AX    16384
#define SM_P1    16448
#define SM_Q1    16480
#define SM_BG1   16512
#define SM_P2    16544
#define SM_Q2    16608
#define SM_BG2   16672
#define SM_PS2   16736
#define SM_QS2   16800
#define SM_COEF  16864    // coeff[0..14], [15]=csum
#define SM_TOTAL 16880

__global__ void __launch_bounds__(256, 1)
main_kernel(const float* __restrict__ L, const float* __restrict__ X,
            const float* __restrict__ bg1, const float* __restrict__ Wg2,
            const float* __restrict__ bg2, const float* __restrict__ Ws2) {
    extern __shared__ float sm[];
    const uint32_t smb = (uint32_t)__cvta_generic_to_shared(sm);
    float* Lt   = sm + SM_LT;
    float* Xs   = sm + SM_XS;
    float* St   = sm + SM_ST;
    float* rowL = sm + SM_ROWL;
    float* axs  = sm + SM_AX;
    float* coef = sm + SM_COEF;

    const int tid = threadIdx.x;
    const int b = blockIdx.x;
    const float* Lb = L + (size_t)b * 4096;
    const float* Xb = X + (size_t)b * (TSTEPS * 64);

    // ---- load L transposed ----
    {
        int n  = tid >> 2;
        int m0 = (tid & 3) * 16;
        #pragma unroll
        for (int q = 0; q < 4; q++) {
            float4 v = *(const float4*)(Lb + n * 64 + m0 + q * 4);
            Lt[(m0 + q * 4 + 0) * 64 + n] = v.x;
            Lt[(m0 + q * 4 + 1) * 64 + n] = v.y;
            Lt[(m0 + q * 4 + 2) * 64 + n] = v.z;
            Lt[(m0 + q * 4 + 3) * 64 + n] = v.w;
        }
    }
    for (int i = tid; i < TSTEPS * 64; i += 256) Xs[i] = Xb[i];
    // Wg2 duplicated
    #pragma unroll
    for (int k = 0; k < 8; k++) {
        int idx = tid + k * 256;
        int f = idx >> 6, c = idx & 63;
        float w = Wg2[f * 64 + c];
        *(float2*)(sm + SM_WG2D + f * 128 + 2 * c) = make_float2(w, w);
    }
    if (tid < 32) {
        sm[SM_P1 + tid]  = g_const[tid];
        sm[SM_Q1 + tid]  = g_const[32 + tid];
        sm[SM_BG1 + tid] = bg1[tid];
    } else if (tid < 96) {
        int g = tid - 32;
        sm[SM_P2 + g]  = g_const[128 + g];
        sm[SM_Q2 + g]  = g_const[192 + g];
        sm[SM_PS2 + g] = g_const[256 + g];
        sm[SM_QS2 + g] = g_const[320 + g];
        sm[SM_BG2 + g] = bg2[g];
    } else if (tid < 112) {
        coef[tid - 96] = g_const[384 + (tid - 96)];
    }
    __syncthreads();

    // ---- St[t][n] = sum_m L[n,m] X[t,m]; rowL[n] ----
    #pragma unroll
    for (int k = 0; k < 4; k++) {
        int idx = tid + k * 256;
        int n = idx & 63, tt = idx >> 6;
        float acc = 0.f;
        if (tt < TSTEPS) {
            const float* xr = Xs + tt * 64;
            #pragma unroll 8
            for (int m = 0; m < 64; m++) acc += Lt[m * 64 + n] * xr[m];
            St[tt * 64 + n] = acc;
        } else {
            #pragma unroll 8
            for (int m = 0; m < 64; m++) acc += Lt[m * 64 + n];
            rowL[n] = acc;
        }
    }
    __syncthreads();

    // ---- hoisted per-thread constants ----
    const int lane = tid & 31, wA = tid >> 5;        // phase1: f=lane, nodes wA*8+i
    const float p1f  = sm[SM_P1 + lane];
    const float q1f  = sm[SM_Q1 + lane];
    const float bg1f = sm[SM_BG1 + lane];
    const u64 p1dup = pk(p1f, p1f);
    u64 base1p[4];
    #pragma unroll
    for (int i2 = 0; i2 < 4; i2++) {
        int n0 = wA * 8 + i2 * 2;
        base1p[i2] = pk(rowL[n0] * q1f + bg1f, rowL[n0 + 1] * q1f + bg1f);
    }
    float m1[3][8], a1[8];
    #pragma unroll
    for (int i = 0; i < 8; i++) { m1[0][i] = m1[1][i] = m1[2][i] = a1[i] = 0.f; }

    const int iB = tid & 15, jB = tid >> 4;          // GEMM layouts
    u64 p2d[4], base2p[2][4];
    #pragma unroll
    for (int c = 0; c < 4; c++) {
        int jc = jB * 4 + c;
        float p2v = sm[SM_P2 + jc], q2v = sm[SM_Q2 + jc], bgv = sm[SM_BG2 + jc];
        p2d[c] = pk(p2v, p2v);
        #pragma unroll
        for (int p = 0; p < 2; p++) {
            int r0 = iB * 4 + p * 2;
            base2p[p][c] = pk(rowL[r0] * q2v + bgv, rowL[r0 + 1] * q2v + bgv);
        }
    }
    float m2[3][16], a2[16];
    #pragma unroll
    for (int e = 0; e < 16; e++) { m2[0][e] = m2[1][e] = m2[2][e] = a2[e] = 0.f; }

    // byte-address bases
    const uint32_t bLT  = smb + SM_LT * 4;
    const uint32_t bS1D = smb + SM_S1D * 4;
    const uint32_t bPT  = smb + SM_PT * 4;
    const uint32_t bWG  = smb + SM_WG2D * 4;
    const uint32_t bST  = smb + SM_ST * 4;

    const uint32_t lAddr = bLT + iB * 16;
    const uint32_t sAddr = bS1D + jB * 16;
    const uint32_t wAddr = bWG + jB * 32;
    const uint32_t pAddr = bPT + iB * 16;

    // ======================= time loop =======================
    for (int t = 0; t < TSTEPS; t++) {
        const float ct = coef[t];
        const uint32_t stRow = bST + t * 256;

        // ---- phase 1 ----
        #pragma unroll
        for (int i2 = 0; i2 < 4; i2++) {
            int n0 = wA * 8 + i2 * 2;
            u64 Sp = lds1(stRow + n0 * 4);
            u64 curp = f2(Sp, p1dup, base1p[i2]);
            float c0, c1; upk(curp, c0, c1);
            #pragma unroll
            for (int h = 0; h < 2; h++) {
                float cur = h ? c1 : c0;
                int u = i2 * 2 + h;
                float s = 0.f;
                s += lif_step(m1[0][u], cur, 0.80f, 0.8f);
                s += lif_step(m1[1][u], cur, 0.90f, 1.0f);
                s += lif_step(m1[2][u], cur, 0.95f, 1.5f);
                a1[u] += ct * s;
                *(float2*)(sm + SM_S1D + (n0 + h) * 64 + 2 * lane) = make_float2(s, s);
            }
        }
        __syncthreads();

        // ---- phase 2: P = L @ s1  (packed, 4x2 tile as 4 f32x2 accs) ----
        u64 A00 = 0, A10 = 0, A01 = 0, A11 = 0;
        #pragma unroll
        for (int m = 0; m < 64; m++) {
            u64 l01, l23, d0, d1;
            lds2(l01, l23, lAddr + m * 256);
            lds2(d0, d1, sAddr + m * 256);
            A00 = f2(l01, d0, A00);
            A10 = f2(l23, d0, A10);
            A01 = f2(l01, d1, A01);
            A11 = f2(l23, d1, A11);
        }
        sts2(bPT + (jB * 2 + 0) * 256 + iB * 16, A00, A10);
        sts2(bPT + (jB * 2 + 1) * 256 + iB * 16, A01, A11);
        __syncthreads();

        // ---- phase 3: cur2 = P @ Wg2 + rank-1; triple LIF2 ----
        u64 C[2][4];
        #pragma unroll
        for (int p = 0; p < 2; p++)
            #pragma unroll
            for (int c = 0; c < 4; c++) C[p][c] = 0;

        #pragma unroll
        for (int f = 0; f < 32; f++) {
            u64 p01, p23, w0, w1, w2, w3;
            lds2(p01, p23, pAddr + f * 256);
            lds2(w0, w1, wAddr + f * 512);
            lds2(w2, w3, wAddr + f * 512 + 16);
            C[0][0] = f2(p01, w0, C[0][0]);  C[1][0] = f2(p23, w0, C[1][0]);
            C[0][1] = f2(p01, w1, C[0][1]);  C[1][1] = f2(p23, w1, C[1][1]);
            C[0][2] = f2(p01, w2, C[0][2]);  C[1][2] = f2(p23, w2, C[1][2]);
            C[0][3] = f2(p01, w3, C[0][3]);  C[1][3] = f2(p23, w3, C[1][3]);
        }
        u64 sc01, sc23;
        lds2(sc01, sc23, stRow + iB * 16);
        #pragma unroll
        for (int p = 0; p < 2; p++) {
            u64 scp = p ? sc23 : sc01;
            #pragma unroll
            for (int c = 0; c < 4; c++) {
                u64 curp = f2(scp, p2d[c], add2(C[p][c], base2p[p][c]));
                float c0, c1; upk(curp, c0, c1);
                #pragma unroll
                for (int h = 0; h < 2; h++) {
                    float cur = h ? c1 : c0;
                    int e = (p * 2 + h) * 4 + c;
                    float s = 0.f;
                    s += lif_step(m2[0][e], cur, 0.80f, 0.8f);
                    s += lif_step(m2[1][e], cur, 0.90f, 1.0f);
                    s += lif_step(m2[2][e], cur, 0.95f, 1.5f);
                    a2[e] += ct * s;
                }
            }
        }
    }

    // ======================= epilogue =======================
    __syncthreads();
    #pragma unroll
    for (int i = 0; i < 8; i++)                 // A1t[f][n] = a1
        sm[SM_PT + lane * 64 + wA * 8 + i] = a1[i];
    #pragma unroll
    for (int k = 0; k < 8; k++) {               // Ws2 dup into S1D buffer
        int idx = tid + k * 256;
        int f = idx >> 6, c = idx & 63;
        float w = Ws2[f * 64 + c];
        *(float2*)(sm + SM_S1D + f * 128 + 2 * c) = make_float2(w, w);
    }
    if (tid < 64) {                             // ax[n] = sum_t coef[t] X[t,n]
        float acc = 0.f;
        #pragma unroll
        for (int t = 0; t < TSTEPS; t++) acc += coef[t] * Xs[t * 64 + tid];
        axs[tid] = acc;
    }
    __syncthreads();

    u64 D[2][4];
    #pragma unroll
    for (int p = 0; p < 2; p++)
        #pragma unroll
        for (int c = 0; c < 4; c++)
            D[p][c] = pk(a2[(p * 2) * 4 + c], a2[(p * 2 + 1) * 4 + c]);

    #pragma unroll
    for (int f = 0; f < 32; f++) {              // + acc1 @ Ws2 (dup in S1D)
        u64 p01, p23, w0, w1, w2, w3;
        lds2(p01, p23, pAddr + f * 256);
        lds2(w0, w1, bS1D + jB * 32 + f * 512);
        lds2(w2, w3, bS1D + jB * 32 + f * 512 + 16);
        D[0][0] = f2(p01, w0, D[0][0]);  D[1][0] = f2(p23, w0, D[1][0]);
        D[0][1] = f2(p01, w1, D[0][1]);  D[1][1] = f2(p23, w1, D[1][1]);
        D[0][2] = f2(p01, w2, D[0][2]);  D[1][2] = f2(p23, w2, D[1][2]);
        D[0][3] = f2(p01, w3, D[0][3]);  D[1][3] = f2(p23, w3, D[1][3]);
    }
    const float csum = coef[15];
    float ps2c[4], qs2c[4];
    #pragma unroll
    for (int c = 0; c < 4; c++) {
        ps2c[c] = sm[SM_PS2 + jB * 4 + c];
        qs2c[c] = sm[SM_QS2 + jB * 4 + c];
    }
    #pragma unroll
    for (int p = 0; p < 2; p++) {
        float v[2][4];
        #pragma unroll
        for (int c = 0; c < 4; c++) upk(D[p][c], v[0][c], v[1][c]);
        #pragma unroll
        for (int h = 0; h < 2; h++) {
            int n = iB * 4 + p * 2 + h;
            float axv = axs[n];
            float4 o;
            o.x = v[h][0] + axv * ps2c[0] + csum * qs2c[0];
            o.y = v[h][1] + axv * ps2c[1] + csum * qs2c[1];
            o.z = v[h][2] + axv * ps2c[2] + csum * qs2c[2];
            o.w = v[h][3] + axv * ps2c[3] + csum * qs2c[3];
            *(float4*)(g_dp + (size_t)b * 4096 + n * 64 + jB * 4) = o;
        }
    }
}

// ---------------------------------------------------------------------------
// decoder: out = relu(dp @ Wc1 + bc1) @ Wc2 + bc2   [2048,4096]->[2048,4]
__global__ void __launch_bounds__(256)
decoder_kernel(const float* __restrict__ Wc1, const float* __restrict__ bc1,
               const float* __restrict__ Wc2, const float* __restrict__ bc2,
               float* __restrict__ out) {
    __shared__ float Wc1s[64 * 128];
    __shared__ float dpT[64 * 16];
    __shared__ float hs[16 * 128];
    __shared__ float Wc2s[128 * 4];
    __shared__ float bc1s[128];

    const int tid = threadIdx.x;
    const int b0 = blockIdx.x * 16;
    if (tid < 128) bc1s[tid] = bc1[tid];
    for (int i = tid; i < 512; i += 256) Wc2s[i] = Wc2[i];

    const int j = tid & 127, rh = tid >> 7;
    const uint32_t bDP = (uint32_t)__cvta_generic_to_shared(dpT);
    u64 hp[4];
    #pragma unroll
    for (int r = 0; r < 4; r++) hp[r] = 0;

    for (int k0 = 0; k0 < 4096; k0 += 64) {
        __syncthreads();
        #pragma unroll
        for (int p = 0; p < 8; p++) {
            int f4 = tid + p * 256;
            int kk = f4 >> 5, jq = f4 & 31;
            *(float4*)(Wc1s + kk * 128 + jq * 4) =
                *(const float4*)(Wc1 + (size_t)(k0 + kk) * 128 + jq * 4);
        }
        {
            int r = tid >> 4, kq = tid & 15;
            float4 v = *(const float4*)(g_dp + (size_t)(b0 + r) * 4096 + k0 + kq * 4);
            dpT[(kq * 4 + 0) * 16 + r] = v.x;
            dpT[(kq * 4 + 1) * 16 + r] = v.y;
            dpT[(kq * 4 + 2) * 16 + r] = v.z;
            dpT[(kq * 4 + 3) * 16 + r] = v.w;
        }
        __syncthreads();
        #pragma unroll 8
        for (int kk = 0; kk < 64; kk++) {
            float w = Wc1s[kk * 128 + j];
            u64 wd = pk(w, w);
            u64 d0, d1, d2, d3;
            lds2(d0, d1, bDP + kk * 64 + rh * 32);
            lds2(d2, d3, bDP + kk * 64 + rh * 32 + 16);
            hp[0] = f2(d0, wd, hp[0]);
            hp[1] = f2(d1, wd, hp[1]);
            hp[2] = f2(d2, wd, hp[2]);
            hp[3] = f2(d3, wd, hp[3]);
        }
    }
    __syncthreads();
    #pragma unroll
    for (int r = 0; r < 4; r++) {
        float lo, hi; upk(hp[r], lo, hi);
        float v0 = lo + bc1s[j], v1 = hi + bc1s[j];
        hs[(rh * 8 + r * 2 + 0) * 128 + j] = v0 > 0.f ? v0 : 0.f;
        hs[(rh * 8 + r * 2 + 1) * 128 + j] = v1 > 0.f ? v1 : 0.f;
    }
    __syncthreads();
    if (tid < 64) {
        int r = tid >> 2, c = tid & 3;
        float acc = bc2[c];
        #pragma unroll 8
        for (int jj = 0; jj < 128; jj++) acc += hs[r * 128 + jj] * Wc2s[jj * 4 + c];
        out[(b0 + r) * 4 + c] = acc;
    }
}

// ---------------------------------------------------------------------------
extern "C" void kernel_launch(void* const* d_in, const int* in_sizes, int n_in,
                              void* d_out, int out_size) {
    const float* L     = (const float*)d_in[0];
    const float* X     = (const float*)d_in[1];
    const float* Wproj = (const float*)d_in[2];
    const float* bproj = (const float*)d_in[3];
    const float* Wg1   = (const float*)d_in[4];
    const float* bg1   = (const float*)d_in[5];
    const float* Ws1   = (const float*)d_in[6];
    const float* bs1   = (const float*)d_in[7];
    const float* Wg2   = (const float*)d_in[8];
    const float* bg2   = (const float*)d_in[9];
    const float* Ws2   = (const float*)d_in[10];
    const float* bs2   = (const float*)d_in[11];
    const float* Wc1   = (const float*)d_in[12];
    const float* bc1   = (const float*)d_in[13];
    const float* Wc2   = (const float*)d_in[14];
    const float* bc2   = (const float*)d_in[15];
    float* out = (float*)d_out;

    int B = in_sizes[0] / 4096;
    if (B > 2048) B = 2048;

    static const size_t smem_bytes = SM_TOTAL * sizeof(float);
    cudaFuncSetAttribute(main_kernel, cudaFuncAttributeMaxDynamicSharedMemorySize,
                         (int)smem_bytes);

    prep_kernel<<<1, 64>>>(Wproj, bproj, Wg1, Ws1, bs1, Wg2, Ws2, bs2);
    main_kernel<<<B, 256, smem_bytes>>>(L, X, bg1, Wg2, bg2, Ws2);
    decoder_kernel<<<B / 16, 256>>>(Wc1, bc1, Wc2, bc2, out);
}

// round 4
// speedup vs baseline: 1.1086x; 1.0003x over previous
#include <cuda_runtime.h>
#include <cstdint>

// ---------------------------------------------------------------------------
// RiemannianGraph_HRSNN — spiking GCN, T=15, B=2048, N=64.
// Round 3: packed fp32 (fma.rn.f32x2 / FFMA2) GEMMs with duplicated-operand
// smem layouts; bitwise-identical math order vs R1. (R2 compile fix.)
// ---------------------------------------------------------------------------

#define TSTEPS 15

__device__ float g_dp[2048 * 4096];
__device__ float g_const[512];

typedef unsigned long long u64;

__device__ __forceinline__ u64 pk(float lo, float hi) {
    u64 d; asm("mov.b64 %0,{%1,%2};" : "=l"(d) : "f"(lo), "f"(hi)); return d;
}
__device__ __forceinline__ void upk(u64 v, float& lo, float& hi) {
    asm("mov.b64 {%0,%1},%2;" : "=f"(lo), "=f"(hi) : "l"(v));
}
__device__ __forceinline__ u64 f2(u64 a, u64 b, u64 c) {
    u64 d; asm("fma.rn.f32x2 %0,%1,%2,%3;" : "=l"(d) : "l"(a), "l"(b), "l"(c)); return d;
}
__device__ __forceinline__ u64 add2(u64 a, u64 b) {
    u64 d; asm("add.rn.f32x2 %0,%1,%2;" : "=l"(d) : "l"(a), "l"(b)); return d;
}
__device__ __forceinline__ void lds2(u64& a, u64& b, uint32_t addr) {
    asm volatile("ld.shared.v2.u64 {%0,%1},[%2];" : "=l"(a), "=l"(b) : "r"(addr));
}
__device__ __forceinline__ u64 lds1(uint32_t addr) {
    u64 a; asm volatile("ld.shared.b64 %0,[%1];" : "=l"(a) : "r"(addr)); return a;
}
__device__ __forceinline__ void sts2(uint32_t addr, u64 a, u64 b) {
    asm volatile("st.shared.v2.u64 [%0],{%1,%2};" :: "r"(addr), "l"(a), "l"(b));
}

// ---------------------------------------------------------------------------
__global__ void prep_kernel(const float* __restrict__ Wproj,
                            const float* __restrict__ bproj,
                            const float* __restrict__ Wg1,
                            const float* __restrict__ Ws1,
                            const float* __restrict__ bs1,
                            const float* __restrict__ Wg2,
                            const float* __restrict__ Ws2,
                            const float* __restrict__ bs2) {
    int t = threadIdx.x;
    if (t < 32) {
        float p1 = 0.f, q1 = 0.f, ps1 = 0.f, cs1 = 0.f;
        #pragma unroll
        for (int k = 0; k < 16; k++) {
            p1  += Wproj[k] * Wg1[k * 32 + t];
            q1  += bproj[k] * Wg1[k * 32 + t];
            ps1 += Wproj[k] * Ws1[k * 32 + t];
            cs1 += bproj[k] * Ws1[k * 32 + t];
        }
        cs1 += bs1[t];
        g_const[t]      = p1;
        g_const[32 + t] = q1;
        g_const[64 + t] = ps1;
        g_const[96 + t] = cs1;
    }
    __syncthreads();
    if (t < 64) {
        float p2 = 0.f, q2 = 0.f, ps2 = 0.f, qs2 = 0.f;
        #pragma unroll
        for (int f = 0; f < 32; f++) {
            float a = g_const[64 + f];
            float c = g_const[96 + f];
            p2  += a * Wg2[f * 64 + t];
            q2  += c * Wg2[f * 64 + t];
            ps2 += a * Ws2[f * 64 + t];
            qs2 += c * Ws2[f * 64 + t];
        }
        qs2 += bs2[t];
        g_const[128 + t] = p2;
        g_const[192 + t] = q2;
        g_const[256 + t] = ps2;
        g_const[320 + t] = qs2;
    }
    if (t == 0) {
        float pw[TSTEPS];
        pw[0] = 1.f;
        for (int k = 1; k < TSTEPS; k++) pw[k] = pw[k - 1] * 0.9f;
        float cs = 0.f;
        for (int tau = 0; tau < TSTEPS; tau++) {
            float late = 0.f, early = 0.f;
            for (int s = 10; s < 15; s++) if (s >= tau) late  += pw[s - tau];
            for (int s = 0;  s < 5;  s++) if (s >= tau) early += pw[s - tau];
            float c = 0.2f * (late - early);
            g_const[384 + tau] = c;
            cs += c;
        }
        g_const[399] = cs;
    }
}

// ---------------------------------------------------------------------------
__device__ __forceinline__ float lif_step(float& m, float cur, float beta, float thr) {
    float r = (m > thr) ? thr : 0.f;
    m = beta * m + (cur - r);
    return (m > thr) ? 1.f : 0.f;
}

// smem float offsets
#define SM_LT    0        // 64x64 Lt[m][n]
#define SM_S1D   4096     // 64x64 dup spikes s1d[m][2j](+1)  (reused: Ws2 dup in epilogue)
#define SM_PT    8192     // 32x64 Pt[f][n]
#define SM_WG2D  10240    // 32x128 dup Wg2
#define SM_ST    14336    // 16x64 St[t][n]
#define SM_XS    15360    // 15x64
#define SM_ROWL  16320
#define SM_AX    16384
#define SM_P1    16448
#define SM_Q1    16480
#define SM_BG1   16512
#define SM_P2    16544
#define SM_Q2    16608
#define SM_BG2   16672
#define SM_PS2   16736
#define SM_QS2   16800
#define SM_COEF  16864    // coeff[0..14], [15]=csum
#define SM_TOTAL 16880

__global__ void __launch_bounds__(256, 1)
main_kernel(const float* __restrict__ L, const float* __restrict__ X,
            const float* __restrict__ bg1, const float* __restrict__ Wg2,
            const float* __restrict__ bg2, const float* __restrict__ Ws2) {
    extern __shared__ float sm[];
    const uint32_t smb = (uint32_t)__cvta_generic_to_shared(sm);
    float* Lt   = sm + SM_LT;
    float* Xs   = sm + SM_XS;
    float* St   = sm + SM_ST;
    float* rowL = sm + SM_ROWL;
    float* axs  = sm + SM_AX;
    float* coef = sm + SM_COEF;

    const int tid = threadIdx.x;
    const int b = blockIdx.x;
    const float* Lb = L + (size_t)b * 4096;
    const float* Xb = X + (size_t)b * (TSTEPS * 64);

    // ---- load L transposed ----
    {
        int n  = tid >> 2;
        int m0 = (tid & 3) * 16;
        #pragma unroll
        for (int q = 0; q < 4; q++) {
            float4 v = *(const float4*)(Lb + n * 64 + m0 + q * 4);
            Lt[(m0 + q * 4 + 0) * 64 + n] = v.x;
            Lt[(m0 + q * 4 + 1) * 64 + n] = v.y;
            Lt[(m0 + q * 4 + 2) * 64 + n] = v.z;
            Lt[(m0 + q * 4 + 3) * 64 + n] = v.w;
        }
    }
    for (int i = tid; i < TSTEPS * 64; i += 256) Xs[i] = Xb[i];
    // Wg2 duplicated
    #pragma unroll
    for (int k = 0; k < 8; k++) {
        int idx = tid + k * 256;
        int f = idx >> 6, c = idx & 63;
        float w = Wg2[f * 64 + c];
        *(float2*)(sm + SM_WG2D + f * 128 + 2 * c) = make_float2(w, w);
    }
    if (tid < 32) {
        sm[SM_P1 + tid]  = g_const[tid];
        sm[SM_Q1 + tid]  = g_const[32 + tid];
        sm[SM_BG1 + tid] = bg1[tid];
    } else if (tid < 96) {
        int g = tid - 32;
        sm[SM_P2 + g]  = g_const[128 + g];
        sm[SM_Q2 + g]  = g_const[192 + g];
        sm[SM_PS2 + g] = g_const[256 + g];
        sm[SM_QS2 + g] = g_const[320 + g];
        sm[SM_BG2 + g] = bg2[g];
    } else if (tid < 112) {
        coef[tid - 96] = g_const[384 + (tid - 96)];
    }
    __syncthreads();

    // ---- St[t][n] = sum_m L[n,m] X[t,m]; rowL[n] ----
    #pragma unroll
    for (int k = 0; k < 4; k++) {
        int idx = tid + k * 256;
        int n = idx & 63, tt = idx >> 6;
        float acc = 0.f;
        if (tt < TSTEPS) {
            const float* xr = Xs + tt * 64;
            #pragma unroll 8
            for (int m = 0; m < 64; m++) acc += Lt[m * 64 + n] * xr[m];
            St[tt * 64 + n] = acc;
        } else {
            #pragma unroll 8
            for (int m = 0; m < 64; m++) acc += Lt[m * 64 + n];
            rowL[n] = acc;
        }
    }
    __syncthreads();

    // ---- hoisted per-thread constants ----
    const int lane = tid & 31, wA = tid >> 5;        // phase1: f=lane, nodes wA*8+i
    const float p1f  = sm[SM_P1 + lane];
    const float q1f  = sm[SM_Q1 + lane];
    const float bg1f = sm[SM_BG1 + lane];
    const u64 p1dup = pk(p1f, p1f);
    u64 base1p[4];
    #pragma unroll
    for (int i2 = 0; i2 < 4; i2++) {
        int n0 = wA * 8 + i2 * 2;
        base1p[i2] = pk(rowL[n0] * q1f + bg1f, rowL[n0 + 1] * q1f + bg1f);
    }
    float m1[3][8], a1[8];
    #pragma unroll
    for (int i = 0; i < 8; i++) { m1[0][i] = m1[1][i] = m1[2][i] = a1[i] = 0.f; }

    const int iB = tid & 15, jB = tid >> 4;          // GEMM layouts
    u64 p2d[4], base2p[2][4];
    #pragma unroll
    for (int c = 0; c < 4; c++) {
        int jc = jB * 4 + c;
        float p2v = sm[SM_P2 + jc], q2v = sm[SM_Q2 + jc], bgv = sm[SM_BG2 + jc];
        p2d[c] = pk(p2v, p2v);
        #pragma unroll
        for (int p = 0; p < 2; p++) {
            int r0 = iB * 4 + p * 2;
            base2p[p][c] = pk(rowL[r0] * q2v + bgv, rowL[r0 + 1] * q2v + bgv);
        }
    }
    float m2[3][16], a2[16];
    #pragma unroll
    for (int e = 0; e < 16; e++) { m2[0][e] = m2[1][e] = m2[2][e] = a2[e] = 0.f; }

    // byte-address bases
    const uint32_t bLT  = smb + SM_LT * 4;
    const uint32_t bS1D = smb + SM_S1D * 4;
    const uint32_t bPT  = smb + SM_PT * 4;
    const uint32_t bWG  = smb + SM_WG2D * 4;
    const uint32_t bST  = smb + SM_ST * 4;

    const uint32_t lAddr = bLT + iB * 16;
    const uint32_t sAddr = bS1D + jB * 16;
    const uint32_t wAddr = bWG + jB * 32;
    const uint32_t pAddr = bPT + iB * 16;

    // ======================= time loop =======================
    for (int t = 0; t < TSTEPS; t++) {
        const float ct = coef[t];
        const uint32_t stRow = bST + t * 256;

        // ---- phase 1 ----
        #pragma unroll
        for (int i2 = 0; i2 < 4; i2++) {
            int n0 = wA * 8 + i2 * 2;
            u64 Sp = lds1(stRow + n0 * 4);
            u64 curp = f2(Sp, p1dup, base1p[i2]);
            float c0, c1; upk(curp, c0, c1);
            #pragma unroll
            for (int h = 0; h < 2; h++) {
                float cur = h ? c1 : c0;
                int u = i2 * 2 + h;
                float s = 0.f;
                s += lif_step(m1[0][u], cur, 0.80f, 0.8f);
                s += lif_step(m1[1][u], cur, 0.90f, 1.0f);
                s += lif_step(m1[2][u], cur, 0.95f, 1.5f);
                a1[u] += ct * s;
                *(float2*)(sm + SM_S1D + (n0 + h) * 64 + 2 * lane) = make_float2(s, s);
            }
        }
        __syncthreads();

        // ---- phase 2: P = L @ s1  (packed, 4x2 tile as 4 f32x2 accs) ----
        u64 A00 = 0, A10 = 0, A01 = 0, A11 = 0;
        #pragma unroll
        for (int m = 0; m < 64; m++) {
            u64 l01, l23, d0, d1;
            lds2(l01, l23, lAddr + m * 256);
            lds2(d0, d1, sAddr + m * 256);
            A00 = f2(l01, d0, A00);
            A10 = f2(l23, d0, A10);
            A01 = f2(l01, d1, A01);
            A11 = f2(l23, d1, A11);
        }
        sts2(bPT + (jB * 2 + 0) * 256 + iB * 16, A00, A10);
        sts2(bPT + (jB * 2 + 1) * 256 + iB * 16, A01, A11);
        __syncthreads();

        // ---- phase 3: cur2 = P @ Wg2 + rank-1; triple LIF2 ----
        u64 C[2][4];
        #pragma unroll
        for (int p = 0; p < 2; p++)
            #pragma unroll
            for (int c = 0; c < 4; c++) C[p][c] = 0;

        #pragma unroll
        for (int f = 0; f < 32; f++) {
            u64 p01, p23, w0, w1, w2, w3;
            lds2(p01, p23, pAddr + f * 256);
            lds2(w0, w1, wAddr + f * 512);
            lds2(w2, w3, wAddr + f * 512 + 16);
            C[0][0] = f2(p01, w0, C[0][0]);  C[1][0] = f2(p23, w0, C[1][0]);
            C[0][1] = f2(p01, w1, C[0][1]);  C[1][1] = f2(p23, w1, C[1][1]);
            C[0][2] = f2(p01, w2, C[0][2]);  C[1][2] = f2(p23, w2, C[1][2]);
            C[0][3] = f2(p01, w3, C[0][3]);  C[1][3] = f2(p23, w3, C[1][3]);
        }
        u64 sc01, sc23;
        lds2(sc01, sc23, stRow + iB * 16);
        #pragma unroll
        for (int p = 0; p < 2; p++) {
            u64 scp = p ? sc23 : sc01;
            #pragma unroll
            for (int c = 0; c < 4; c++) {
                u64 curp = f2(scp, p2d[c], add2(C[p][c], base2p[p][c]));
                float c0, c1; upk(curp, c0, c1);
                #pragma unroll
                for (int h = 0; h < 2; h++) {
                    float cur = h ? c1 : c0;
                    int e = (p * 2 + h) * 4 + c;
                    float s = 0.f;
                    s += lif_step(m2[0][e], cur, 0.80f, 0.8f);
                    s += lif_step(m2[1][e], cur, 0.90f, 1.0f);
                    s += lif_step(m2[2][e], cur, 0.95f, 1.5f);
                    a2[e] += ct * s;
                }
            }
        }
    }

    // ======================= epilogue =======================
    __syncthreads();
    #pragma unroll
    for (int i = 0; i < 8; i++)                 // A1t[f][n] = a1
        sm[SM_PT + lane * 64 + wA * 8 + i] = a1[i];
    #pragma unroll
    for (int k = 0; k < 8; k++) {               // Ws2 dup into S1D buffer
        int idx = tid + k * 256;
        int f = idx >> 6, c = idx & 63;
        float w = Ws2[f * 64 + c];
        *(float2*)(sm + SM_S1D + f * 128 + 2 * c) = make_float2(w, w);
    }
    if (tid < 64) {                             // ax[n] = sum_t coef[t] X[t,n]
        float acc = 0.f;
        #pragma unroll
        for (int t = 0; t < TSTEPS; t++) acc += coef[t] * Xs[t * 64 + tid];
        axs[tid] = acc;
    }
    __syncthreads();

    u64 D[2][4];
    #pragma unroll
    for (int p = 0; p < 2; p++)
        #pragma unroll
        for (int c = 0; c < 4; c++)
            D[p][c] = pk(a2[(p * 2) * 4 + c], a2[(p * 2 + 1) * 4 + c]);

    #pragma unroll
    for (int f = 0; f < 32; f++) {              // + acc1 @ Ws2 (dup in S1D)
        u64 p01, p23, w0, w1, w2, w3;
        lds2(p01, p23, pAddr + f * 256);
        lds2(w0, w1, bS1D + jB * 32 + f * 512);
        lds2(w2, w3, bS1D + jB * 32 + f * 512 + 16);
        D[0][0] = f2(p01, w0, D[0][0]);  D[1][0] = f2(p23, w0, D[1][0]);
        D[0][1] = f2(p01, w1, D[0][1]);  D[1][1] = f2(p23, w1, D[1][1]);
        D[0][2] = f2(p01, w2, D[0][2]);  D[1][2] = f2(p23, w2, D[1][2]);
        D[0][3] = f2(p01, w3, D[0][3]);  D[1][3] = f2(p23, w3, D[1][3]);
    }
    const float csum = coef[15];
    float ps2c[4], qs2c[4];
    #pragma unroll
    for (int c = 0; c < 4; c++) {
        ps2c[c] = sm[SM_PS2 + jB * 4 + c];
        qs2c[c] = sm[SM_QS2 + jB * 4 + c];
    }
    #pragma unroll
    for (int p = 0; p < 2; p++) {
        float v[2][4];
        #pragma unroll
        for (int c = 0; c < 4; c++) upk(D[p][c], v[0][c], v[1][c]);
        #pragma unroll
        for (int h = 0; h < 2; h++) {
            int n = iB * 4 + p * 2 + h;
            float axv = axs[n];
            float4 o;
            o.x = v[h][0] + axv * ps2c[0] + csum * qs2c[0];
            o.y = v[h][1] + axv * ps2c[1] + csum * qs2c[1];
            o.z = v[h][2] + axv * ps2c[2] + csum * qs2c[2];
            o.w = v[h][3] + axv * ps2c[3] + csum * qs2c[3];
            *(float4*)(g_dp + (size_t)b * 4096 + n * 64 + jB * 4) = o;
        }
    }
}

// ---------------------------------------------------------------------------
// decoder: out = relu(dp @ Wc1 + bc1) @ Wc2 + bc2   [2048,4096]->[2048,4]
__global__ void __launch_bounds__(256)
decoder_kernel(const float* __restrict__ Wc1, const float* __restrict__ bc1,
               const float* __restrict__ Wc2, const float* __restrict__ bc2,
               float* __restrict__ out) {
    __shared__ float Wc1s[64 * 128];
    __shared__ float dpT[64 * 16];
    __shared__ float hs[16 * 128];
    __shared__ float Wc2s[128 * 4];
    __shared__ float bc1s[128];

    const int tid = threadIdx.x;
    const int b0 = blockIdx.x * 16;
    if (tid < 128) bc1s[tid] = bc1[tid];
    for (int i = tid; i < 512; i += 256) Wc2s[i] = Wc2[i];

    const int j = tid & 127, rh = tid >> 7;
    const uint32_t bDP = (uint32_t)__cvta_generic_to_shared(dpT);
    u64 hp[4];
    #pragma unroll
    for (int r = 0; r < 4; r++) hp[r] = 0;

    for (int k0 = 0; k0 < 4096; k0 += 64) {
        __syncthreads();
        #pragma unroll
        for (int p = 0; p < 8; p++) {
            int f4 = tid + p * 256;
            int kk = f4 >> 5, jq = f4 & 31;
            *(float4*)(Wc1s + kk * 128 + jq * 4) =
                *(const float4*)(Wc1 + (size_t)(k0 + kk) * 128 + jq * 4);
        }
        {
            int r = tid >> 4, kq = tid & 15;
            float4 v = *(const float4*)(g_dp + (size_t)(b0 + r) * 4096 + k0 + kq * 4);
            dpT[(kq * 4 + 0) * 16 + r] = v.x;
            dpT[(kq * 4 + 1) * 16 + r] = v.y;
            dpT[(kq * 4 + 2) * 16 + r] = v.z;
            dpT[(kq * 4 + 3) * 16 + r] = v.w;
        }
        __syncthreads();
        #pragma unroll 8
        for (int kk = 0; kk < 64; kk++) {
            float w = Wc1s[kk * 128 + j];
            u64 wd = pk(w, w);
            u64 d0, d1, d2, d3;
            lds2(d0, d1, bDP + kk * 64 + rh * 32);
            lds2(d2, d3, bDP + kk * 64 + rh * 32 + 16);
            hp[0] = f2(d0, wd, hp[0]);
            hp[1] = f2(d1, wd, hp[1]);
            hp[2] = f2(d2, wd, hp[2]);
            hp[3] = f2(d3, wd, hp[3]);
        }
    }
    __syncthreads();
    #pragma unroll
    for (int r = 0; r < 4; r++) {
        float lo, hi; upk(hp[r], lo, hi);
        float v0 = lo + bc1s[j], v1 = hi + bc1s[j];
        hs[(rh * 8 + r * 2 + 0) * 128 + j] = v0 > 0.f ? v0 : 0.f;
        hs[(rh * 8 + r * 2 + 1) * 128 + j] = v1 > 0.f ? v1 : 0.f;
    }
    __syncthreads();
    if (tid < 64) {
        int r = tid >> 2, c = tid & 3;
        float acc = bc2[c];
        #pragma unroll 8
        for (int jj = 0; jj < 128; jj++) acc += hs[r * 128 + jj] * Wc2s[jj * 4 + c];
        out[(b0 + r) * 4 + c] = acc;
    }
}

// ---------------------------------------------------------------------------
extern "C" void kernel_launch(void* const* d_in, const int* in_sizes, int n_in,
                              void* d_out, int out_size) {
    const float* L     = (const float*)d_in[0];
    const float* X     = (const float*)d_in[1];
    const float* Wproj = (const float*)d_in[2];
    const float* bproj = (const float*)d_in[3];
    const float* Wg1   = (const float*)d_in[4];
    const float* bg1   = (const float*)d_in[5];
    const float* Ws1   = (const float*)d_in[6];
    const float* bs1   = (const float*)d_in[7];
    const float* Wg2   = (const float*)d_in[8];
    const float* bg2   = (const float*)d_in[9];
    const float* Ws2   = (const float*)d_in[10];
    const float* bs2   = (const float*)d_in[11];
    const float* Wc1   = (const float*)d_in[12];
    const float* bc1   = (const float*)d_in[13];
    const float* Wc2   = (const float*)d_in[14];
    const float* bc2   = (const float*)d_in[15];
    float* out = (float*)d_out;

    int B = in_sizes[0] / 4096;
    if (B > 2048) B = 2048;

    static const size_t smem_bytes = SM_TOTAL * sizeof(float);
    cudaFuncSetAttribute(main_kernel, cudaFuncAttributeMaxDynamicSharedMemorySize,
                         (int)smem_bytes);

    prep_kernel<<<1, 64>>>(Wproj, bproj, Wg1, Ws1, bs1, Wg2, Ws2, bs2);
    main_kernel<<<B, 256, smem_bytes>>>(L, X, bg1, Wg2, bg2, Ws2);
    decoder_kernel<<<B / 16, 256>>>(Wc1, bc1, Wc2, bc2, out);
}